// round 12
// baseline (speedup 1.0000x reference)
#include <cuda_runtime.h>
#include <cstdint>

#define NROWS  65536
#define DIN    64
#define NC     1024
#define DOUT   256
#define BM     64
#define BK     32
#define NCHUNK (NC / BK)
#define THREADS 256
#define CSTRIDE 68
#define PSTRIDE 36
#define VSTRIDE 36
#define LOG2E  1.4426950408889634f

struct Smem {
    uint32_t ct_hi[2][BK][CSTRIDE];   // centers hi (tf32 bits), [n][d]
    uint32_t ct_lo[2][BK][CSTRIDE];   // centers lo
    uint32_t vt[2][DOUT][VSTRIDE];    // V^T (tf32 bits), [n][k]
    uint32_t p[2][BM][PSTRIDE];       // P (tf32 bits), [m][k]
    float    csq[2][BK];              // sum c^2 s
    float    rowsum[2][BM];           // per-n-half partial row sums
    float    s[DIN];
};

__device__ __forceinline__ uint32_t f2tf32(float f) {
    uint32_t u;
    asm("cvt.rna.tf32.f32 %0, %1;" : "=r"(u) : "f"(f));
    return u;
}
__device__ __forceinline__ float fast_exp2(float f) {
    float r;
    asm("ex2.approx.f32 %0, %1;" : "=f"(r) : "f"(f));
    return r;
}
__device__ __forceinline__ void mma8(float* d, const uint32_t* a,
                                     uint32_t b0, uint32_t b1) {
    asm volatile(
        "mma.sync.aligned.m16n8k8.row.col.f32.tf32.tf32.f32 "
        "{%0,%1,%2,%3}, {%4,%5,%6,%7}, {%8,%9}, {%0,%1,%2,%3};"
        : "+f"(d[0]), "+f"(d[1]), "+f"(d[2]), "+f"(d[3])
        : "r"(a[0]), "r"(a[1]), "r"(a[2]), "r"(a[3]), "r"(b0), "r"(b1));
}

// GEMM2: acc += P(64x32) @ V(32x256); warp tile M32 x N64, conflict-free LDS
__device__ __forceinline__ void gemm2(const Smem& sm, int bb, int rw, int wc,
                                      int grp, int thr, float acc[2][8][4]) {
    uint32_t a[2][4][4];
    #pragma unroll
    for (int mt = 0; mt < 2; mt++) {
        const int m = rw * 32 + mt * 16 + grp;
        #pragma unroll
        for (int kt = 0; kt < 4; kt++) {
            a[mt][kt][0] = sm.p[bb][m][8 * kt + thr];
            a[mt][kt][1] = sm.p[bb][m + 8][8 * kt + thr];
            a[mt][kt][2] = sm.p[bb][m][8 * kt + thr + 4];
            a[mt][kt][3] = sm.p[bb][m + 8][8 * kt + thr + 4];
        }
    }
    #pragma unroll
    for (int nt = 0; nt < 8; nt++) {
        const int n = wc * 64 + nt * 8 + grp;
        #pragma unroll
        for (int kt = 0; kt < 4; kt++) {
            const uint32_t b0 = sm.vt[bb][n][8 * kt + thr];
            const uint32_t b1 = sm.vt[bb][n][8 * kt + thr + 4];
            mma8(acc[0][nt], a[0][kt], b0, b1);
            mma8(acc[1][nt], a[1][kt], b0, b1);
        }
    }
}

__global__ void __launch_bounds__(THREADS, 1)
attnn_kernel(const float* __restrict__ x,
             const float* __restrict__ ctrs,
             const float* __restrict__ values,
             const float* __restrict__ s_in,
             float* __restrict__ out)
{
    extern __shared__ char raw[];
    Smem& sm = *reinterpret_cast<Smem*>(raw);

    const int tid  = threadIdx.x;
    const int lane = tid & 31;
    const int wid  = tid >> 5;
    const int n0   = blockIdx.x * BM;

    // loader mapping
    const int ck = tid >> 3;          // k row 0..31
    const int cd = (tid & 7) * 8;     // ctrs d base
    const int nb = tid & 7;           // V col base

    // mma lane mapping
    const int grp = lane >> 2;
    const int thr = lane & 3;
    // GEMM1 warp mapping: m-tile (16 rows) x n-half (16 cols)
    const int g1m  = (wid & 3) * 16;
    const int half = wid >> 2;
    // GEMM2 warp mapping: m-half (32 rows) x n-quarter (64 cols)
    const int rw = wid >> 2;
    const int wc = wid & 3;

    if (tid < DIN) sm.s[tid] = s_in[tid];
    __syncthreads();

    // ---- stage x (2*s*x) into smem scratch (overlays vt, prologue only) ----
    float* xs = reinterpret_cast<float*>(&sm.vt[0][0][0]);   // [64][68]
    {
        const int r = tid >> 2, q = tid & 3;
        const float* xp = x + (size_t)(n0 + r) * DIN + 16 * q;
        #pragma unroll
        for (int m = 0; m < 4; m++) {
            float4 v = *reinterpret_cast<const float4*>(xp + 4 * m);
            const int d = 16 * q + 4 * m;
            float4 t = make_float4(2.f * v.x * sm.s[d+0], 2.f * v.y * sm.s[d+1],
                                   2.f * v.z * sm.s[d+2], 2.f * v.w * sm.s[d+3]);
            *reinterpret_cast<float4*>(&xs[r * 68 + d]) = t;
        }
    }
    // persistent s slice for csq
    float sreg[8];
    #pragma unroll
    for (int u = 0; u < 8; u++) sreg[u] = sm.s[cd + u];

    // ---- prefetch chunk 0 (LDG overlaps with frag extraction) ----
    float4 cpre0, cpre1;
    float  vpre[32];
    {
        const float* cp = ctrs + (size_t)ck * DIN + cd;
        cpre0 = *reinterpret_cast<const float4*>(cp);
        cpre1 = *reinterpret_cast<const float4*>(cp + 4);
        const float* vp = values + (size_t)ck * DOUT + nb;
        #pragma unroll
        for (int j = 0; j < 32; j++) vpre[j] = vp[8 * j];
    }
    __syncthreads();

    // ---- extract persistent x hi/lo A-fragments (m16k8 x 8 ksteps) ----
    uint32_t xh[8][4], xl[8][4];
    #pragma unroll
    for (int kt = 0; kt < 8; kt++) {
        float v[4];
        v[0] = xs[(g1m + grp)     * 68 + 8 * kt + thr];
        v[1] = xs[(g1m + grp + 8) * 68 + 8 * kt + thr];
        v[2] = xs[(g1m + grp)     * 68 + 8 * kt + thr + 4];
        v[3] = xs[(g1m + grp + 8) * 68 + 8 * kt + thr + 4];
        #pragma unroll
        for (int u = 0; u < 4; u++) {
            xh[kt][u] = f2tf32(v[u]);
            xl[kt][u] = f2tf32(v[u] - __uint_as_float(xh[kt][u]));
        }
    }
    __syncthreads();   // xs scratch free -> vt usable

    float acc[2][8][4];
    #pragma unroll
    for (int mt = 0; mt < 2; mt++)
        #pragma unroll
        for (int nt = 0; nt < 8; nt++)
            #pragma unroll
            for (int u = 0; u < 4; u++) acc[mt][nt][u] = 0.f;
    float sacc0 = 0.f, sacc1 = 0.f;

    for (int c = 0; c < NCHUNK; c++) {
        const int b = c & 1;

        // ---- commit centers hi/lo + csq ----
        {
            uint4 h0, h1, l0, l1;
            h0.x = f2tf32(cpre0.x); l0.x = f2tf32(cpre0.x - __uint_as_float(h0.x));
            h0.y = f2tf32(cpre0.y); l0.y = f2tf32(cpre0.y - __uint_as_float(h0.y));
            h0.z = f2tf32(cpre0.z); l0.z = f2tf32(cpre0.z - __uint_as_float(h0.z));
            h0.w = f2tf32(cpre0.w); l0.w = f2tf32(cpre0.w - __uint_as_float(h0.w));
            h1.x = f2tf32(cpre1.x); l1.x = f2tf32(cpre1.x - __uint_as_float(h1.x));
            h1.y = f2tf32(cpre1.y); l1.y = f2tf32(cpre1.y - __uint_as_float(h1.y));
            h1.z = f2tf32(cpre1.z); l1.z = f2tf32(cpre1.z - __uint_as_float(h1.z));
            h1.w = f2tf32(cpre1.w); l1.w = f2tf32(cpre1.w - __uint_as_float(h1.w));
            *reinterpret_cast<uint4*>(&sm.ct_hi[b][ck][cd])     = h0;
            *reinterpret_cast<uint4*>(&sm.ct_hi[b][ck][cd + 4]) = h1;
            *reinterpret_cast<uint4*>(&sm.ct_lo[b][ck][cd])     = l0;
            *reinterpret_cast<uint4*>(&sm.ct_lo[b][ck][cd + 4]) = l1;
            float part = cpre0.x*cpre0.x*sreg[0] + cpre0.y*cpre0.y*sreg[1]
                       + cpre0.z*cpre0.z*sreg[2] + cpre0.w*cpre0.w*sreg[3]
                       + cpre1.x*cpre1.x*sreg[4] + cpre1.y*cpre1.y*sreg[5]
                       + cpre1.z*cpre1.z*sreg[6] + cpre1.w*cpre1.w*sreg[7];
            part += __shfl_xor_sync(0xffffffffu, part, 4);
            part += __shfl_xor_sync(0xffffffffu, part, 2);
            part += __shfl_xor_sync(0xffffffffu, part, 1);
            if ((tid & 7) == 0) sm.csq[b][ck] = part;
        }
        // ---- commit V transposed (conflict-free STS.32) ----
        #pragma unroll
        for (int j = 0; j < 32; j++)
            sm.vt[b][nb + 8 * j][ck] = f2tf32(vpre[j]);
        __syncthreads();   // sync1: tiles visible

        // ---- prefetch next chunk ----
        if (c + 1 < NCHUNK) {
            const int kb = (c + 1) * BK;
            const float* cp = ctrs + (size_t)(kb + ck) * DIN + cd;
            cpre0 = *reinterpret_cast<const float4*>(cp);
            cpre1 = *reinterpret_cast<const float4*>(cp + 4);
            const float* vp = values + (size_t)(kb + ck) * DOUT + nb;
            #pragma unroll
            for (int j = 0; j < 32; j++) vpre[j] = vp[8 * j];
        }

        // ---- GEMM1: logits via 3xTF32 (M64 x N32 x K64) ----
        float pacc[2][4];
        #pragma unroll
        for (int nt = 0; nt < 2; nt++)
            #pragma unroll
            for (int u = 0; u < 4; u++) pacc[nt][u] = 0.f;
        #pragma unroll
        for (int nt = 0; nt < 2; nt++) {
            const int n = half * 16 + nt * 8 + grp;
            #pragma unroll
            for (int kt = 0; kt < 8; kt++) {
                const uint32_t bh0 = sm.ct_hi[b][n][8 * kt + thr];
                const uint32_t bh1 = sm.ct_hi[b][n][8 * kt + thr + 4];
                const uint32_t bl0 = sm.ct_lo[b][n][8 * kt + thr];
                const uint32_t bl1 = sm.ct_lo[b][n][8 * kt + thr + 4];
                mma8(pacc[nt], xh[kt], bh0, bh1);
                mma8(pacc[nt], xh[kt], bl0, bl1);
                mma8(pacc[nt], xl[kt], bh0, bh1);
            }
        }

        // ---- exp in fragment (x^2 term dropped: softmax-invariant), store P ----
        #pragma unroll
        for (int nt = 0; nt < 2; nt++) {
            const int c0 = half * 16 + nt * 8 + 2 * thr;
            const float2 cq = *reinterpret_cast<const float2*>(&sm.csq[b][c0]);
            uint32_t p0 = f2tf32(fast_exp2((pacc[nt][0] - cq.x) * LOG2E));
            uint32_t p1 = f2tf32(fast_exp2((pacc[nt][1] - cq.y) * LOG2E));
            uint32_t p2 = f2tf32(fast_exp2((pacc[nt][2] - cq.x) * LOG2E));
            uint32_t p3 = f2tf32(fast_exp2((pacc[nt][3] - cq.y) * LOG2E));
            sacc0 += __uint_as_float(p0) + __uint_as_float(p1);
            sacc1 += __uint_as_float(p2) + __uint_as_float(p3);
            *reinterpret_cast<uint2*>(&sm.p[b][g1m + grp][c0])     = make_uint2(p0, p1);
            *reinterpret_cast<uint2*>(&sm.p[b][g1m + grp + 8][c0]) = make_uint2(p2, p3);
        }
        __syncthreads();   // sync2: P visible

        // ---- GEMM2 ----
        gemm2(sm, b, rw, wc, grp, thr, acc);
    }

    // ---- combine row sums: reduce over thr quad, then over 2 n-halves ----
    sacc0 += __shfl_xor_sync(0xffffffffu, sacc0, 1);
    sacc0 += __shfl_xor_sync(0xffffffffu, sacc0, 2);
    sacc1 += __shfl_xor_sync(0xffffffffu, sacc1, 1);
    sacc1 += __shfl_xor_sync(0xffffffffu, sacc1, 2);
    if (thr == 0) {
        sm.rowsum[half][g1m + grp]     = sacc0;
        sm.rowsum[half][g1m + grp + 8] = sacc1;
    }
    __syncthreads();

    // ---- epilogue: normalize + store ----
    #pragma unroll
    for (int mt = 0; mt < 2; mt++) {
        const int row0 = rw * 32 + mt * 16 + grp;
        const float inv0 = 1.0f / (sm.rowsum[0][row0]     + sm.rowsum[1][row0]);
        const float inv1 = 1.0f / (sm.rowsum[0][row0 + 8] + sm.rowsum[1][row0 + 8]);
        float* o0 = out + (size_t)(n0 + row0) * DOUT;
        float* o1 = out + (size_t)(n0 + row0 + 8) * DOUT;
        #pragma unroll
        for (int nt = 0; nt < 8; nt++) {
            const int col = wc * 64 + nt * 8 + 2 * thr;
            *reinterpret_cast<float2*>(o0 + col) =
                make_float2(acc[mt][nt][0] * inv0, acc[mt][nt][1] * inv0);
            *reinterpret_cast<float2*>(o1 + col) =
                make_float2(acc[mt][nt][2] * inv1, acc[mt][nt][3] * inv1);
        }
    }
}

extern "C" void kernel_launch(void* const* d_in, const int* in_sizes, int n_in,
                              void* d_out, int out_size)
{
    const float* x      = (const float*)d_in[0];   // (65536, 64)
    const float* ctrs   = (const float*)d_in[1];   // (1024, 64)
    const float* values = (const float*)d_in[2];   // (1024, 256)
    const float* s      = (const float*)d_in[3];   // (64,)
    float* out          = (float*)d_out;           // (65536, 256)

    const int smem_bytes = (int)sizeof(Smem);
    cudaFuncSetAttribute(attnn_kernel,
                         cudaFuncAttributeMaxDynamicSharedMemorySize, smem_bytes);
    attnn_kernel<<<NROWS / BM, THREADS, smem_bytes>>>(x, ctrs, values, s, out);
}

// round 14
// speedup vs baseline: 1.5516x; 1.5516x over previous
#include <cuda_runtime.h>
#include <cuda_fp16.h>
#include <cstdint>

#define NROWS  65536
#define DIN    64
#define NC     1024
#define DOUT   256
#define BM     64
#define BK     32
#define NCHUNK (NC / BK)
#define THREADS 256
#define LOG2E  1.4426950408889634f

struct Smem {
    uint32_t cth[2][BK][36];     // centers hi (fp16x2 over d-pairs), [n][e]
    uint32_t ctl[2][BK][36];     // centers lo
    uint32_t vt2[2][DOUT][20];   // V (fp16x2 over k-pairs), [n][e]
    uint32_t p2[2][BM][20];      // P (fp16x2 over k-pairs), [m][e]
    float    csq2[2][BK];        // (sum c^2 s) * log2(e)
    float    halfmax[2][BM];     // per-half chunk row max (log2 domain)
    float    factor[BM];         // acc rescale factor per row
    float    rowsum[2][BM];
    float    s[DIN];
};

__device__ __forceinline__ float fast_exp2(float f) {
    float r; asm("ex2.approx.f32 %0, %1;" : "=f"(r) : "f"(f)); return r;
}
__device__ __forceinline__ uint32_t pack_h2(float lo, float hi) {
    uint32_t d; asm("cvt.rn.f16x2.f32 %0, %1, %2;" : "=r"(d) : "f"(hi), "f"(lo)); return d;
}
__device__ __forceinline__ float2 h2f2(uint32_t h) {
    __half2 hh = *reinterpret_cast<__half2*>(&h);
    return __half22float2(hh);
}
__device__ __forceinline__ void mma16(float* d, const uint32_t* a,
                                      uint32_t b0, uint32_t b1) {
    asm volatile(
        "mma.sync.aligned.m16n8k16.row.col.f32.f16.f16.f32 "
        "{%0,%1,%2,%3}, {%4,%5,%6,%7}, {%8,%9}, {%0,%1,%2,%3};"
        : "+f"(d[0]), "+f"(d[1]), "+f"(d[2]), "+f"(d[3])
        : "r"(a[0]), "r"(a[1]), "r"(a[2]), "r"(a[3]), "r"(b0), "r"(b1));
}

__global__ void __launch_bounds__(THREADS, 1)
attnn_kernel(const float* __restrict__ x,
             const float* __restrict__ ctrs,
             const float* __restrict__ values,
             const float* __restrict__ s_in,
             float* __restrict__ out)
{
    extern __shared__ char raw[];
    Smem& sm = *reinterpret_cast<Smem*>(raw);

    const int tid  = threadIdx.x;
    const int lane = tid & 31;
    const int wid  = tid >> 5;
    const int n0   = blockIdx.x * BM;

    // loader mapping
    const int ck = tid >> 3;          // ctr row 0..31
    const int c8 = tid & 7;           // ctr d-octet
    // mma lane mapping
    const int grp = lane >> 2;
    const int thr = lane & 3;
    // GEMM1 warp mapping: m-tile (16 rows) x n-half (16 ctrs)
    const int g1m  = (wid & 3) * 16;
    const int half = wid >> 2;
    const int r0 = g1m + grp, r1 = r0 + 8;
    // GEMM2 warp mapping: m-half (32 rows) x n-quarter (64 cols)
    const int rw = wid >> 2;
    const int wc = wid & 3;

    if (tid < DIN) sm.s[tid] = s_in[tid];
    __syncthreads();

    // ---- stage scaled x (2*log2e*s*x) into scratch overlaying vt2 ----
    float* xs = reinterpret_cast<float*>(&sm.vt2[0][0][0]);   // [64][68]
    {
        const int r = tid >> 2, q = tid & 3;
        const float* xp = x + (size_t)(n0 + r) * DIN + 16 * q;
        #pragma unroll
        for (int m = 0; m < 4; m++) {
            float4 v = *reinterpret_cast<const float4*>(xp + 4 * m);
            const int d = 16 * q + 4 * m;
            const float kf = 2.0f * LOG2E;
            float4 t = make_float4(kf * v.x * sm.s[d+0], kf * v.y * sm.s[d+1],
                                   kf * v.z * sm.s[d+2], kf * v.w * sm.s[d+3]);
            *reinterpret_cast<float4*>(&xs[r * 68 + d]) = t;
        }
    }
    float sreg[8];
    #pragma unroll
    for (int u = 0; u < 8; u++) sreg[u] = sm.s[c8 * 8 + u];

    // ---- prefetch chunk 0 ----
    float4 cpre0, cpre1;
    uint32_t vhalf[16];
    {
        const float* cp = ctrs + (size_t)ck * DIN + c8 * 8;
        cpre0 = *reinterpret_cast<const float4*>(cp);
        cpre1 = *reinterpret_cast<const float4*>(cp + 4);
        const float* vp = values + tid;
        #pragma unroll
        for (int e = 0; e < 16; e++) {
            float f0 = vp[(size_t)(2 * e) * DOUT];
            float f1 = vp[(size_t)(2 * e + 1) * DOUT];
            vhalf[e] = pack_h2(f0, f1);
        }
    }
    __syncthreads();

    // ---- persistent x hi/lo fp16 A-fragments (4 k16 steps) ----
    uint32_t ah[4][4], al[4][4];
    #pragma unroll
    for (int kt = 0; kt < 4; kt++) {
        #pragma unroll
        for (int rr = 0; rr < 2; rr++) {
            const int m = (rr ? r1 : r0);
            float2 v0 = *reinterpret_cast<const float2*>(&xs[m * 68 + 2 * thr + 16 * kt]);
            float2 v1 = *reinterpret_cast<const float2*>(&xs[m * 68 + 2 * thr + 8 + 16 * kt]);
            uint32_t h0 = pack_h2(v0.x, v0.y);
            float2 hf0 = h2f2(h0);
            uint32_t l0 = pack_h2(v0.x - hf0.x, v0.y - hf0.y);
            uint32_t h1 = pack_h2(v1.x, v1.y);
            float2 hf1 = h2f2(h1);
            uint32_t l1 = pack_h2(v1.x - hf1.x, v1.y - hf1.y);
            ah[kt][rr] = h0; ah[kt][rr + 2] = h1;
            al[kt][rr] = l0; al[kt][rr + 2] = l1;
        }
    }
    __syncthreads();   // scratch free

    float acc[2][8][4];
    #pragma unroll
    for (int mt = 0; mt < 2; mt++)
        #pragma unroll
        for (int nt = 0; nt < 8; nt++)
            #pragma unroll
            for (int u = 0; u < 4; u++) acc[mt][nt][u] = 0.f;
    float sacc0 = 0.f, sacc1 = 0.f;
    float M0 = -1e30f, M1 = -1e30f;   // running row max (log2 domain)

    for (int c = 0; c < NCHUNK; c++) {
        const int b = c & 1;

        // ---- commit centers hi/lo (fp16 split) + csq2 ----
        {
            float cv[8] = {cpre0.x, cpre0.y, cpre0.z, cpre0.w,
                           cpre1.x, cpre1.y, cpre1.z, cpre1.w};
            uint32_t hw[4], lw[4];
            #pragma unroll
            for (int w = 0; w < 4; w++) {
                hw[w] = pack_h2(cv[2*w], cv[2*w+1]);
                float2 hf = h2f2(hw[w]);
                lw[w] = pack_h2(cv[2*w] - hf.x, cv[2*w+1] - hf.y);
            }
            *reinterpret_cast<uint4*>(&sm.cth[b][ck][c8 * 4]) =
                make_uint4(hw[0], hw[1], hw[2], hw[3]);
            *reinterpret_cast<uint4*>(&sm.ctl[b][ck][c8 * 4]) =
                make_uint4(lw[0], lw[1], lw[2], lw[3]);
            float part = 0.f;
            #pragma unroll
            for (int u = 0; u < 8; u++) part += cv[u] * cv[u] * sreg[u];
            part += __shfl_xor_sync(0xffffffffu, part, 1);
            part += __shfl_xor_sync(0xffffffffu, part, 2);
            part += __shfl_xor_sync(0xffffffffu, part, 4);
            if (c8 == 0) sm.csq2[b][ck] = part * LOG2E;
        }
        // ---- commit V (thread owns column n=tid): 4 STS.128 ----
        #pragma unroll
        for (int j = 0; j < 4; j++)
            *reinterpret_cast<uint4*>(&sm.vt2[b][tid][4 * j]) =
                make_uint4(vhalf[4*j], vhalf[4*j+1], vhalf[4*j+2], vhalf[4*j+3]);
        __syncthreads();   // sync1: tiles visible

        // ---- prefetch next chunk ----
        if (c + 1 < NCHUNK) {
            const int kb = (c + 1) * BK;
            const float* cp = ctrs + (size_t)(kb + ck) * DIN + c8 * 8;
            cpre0 = *reinterpret_cast<const float4*>(cp);
            cpre1 = *reinterpret_cast<const float4*>(cp + 4);
            const float* vp = values + (size_t)kb * DOUT + tid;
            #pragma unroll
            for (int e = 0; e < 16; e++) {
                float f0 = vp[(size_t)(2 * e) * DOUT];
                float f1 = vp[(size_t)(2 * e + 1) * DOUT];
                vhalf[e] = pack_h2(f0, f1);
            }
        }

        // ---- GEMM1: logits via fp16 2-term split (M64 x N32 x K64) ----
        float pacc[2][4];
        #pragma unroll
        for (int nt = 0; nt < 2; nt++)
            #pragma unroll
            for (int u = 0; u < 4; u++) pacc[nt][u] = 0.f;
        #pragma unroll
        for (int nt = 0; nt < 2; nt++) {
            const int n = half * 16 + nt * 8 + grp;
            #pragma unroll
            for (int kt = 0; kt < 4; kt++) {
                const uint32_t bh0 = sm.cth[b][n][8 * kt + thr];
                const uint32_t bh1 = sm.cth[b][n][8 * kt + thr + 4];
                const uint32_t bl0 = sm.ctl[b][n][8 * kt + thr];
                const uint32_t bl1 = sm.ctl[b][n][8 * kt + thr + 4];
                mma16(pacc[nt], ah[kt], bh0, bh1);
                mma16(pacc[nt], ah[kt], bl0, bl1);
                mma16(pacc[nt], al[kt], bh0, bh1);
            }
        }

        // ---- logits (log2 domain), per-row chunk max ----
        float ll[2][4];
        #pragma unroll
        for (int nt = 0; nt < 2; nt++) {
            const int cc = half * 16 + nt * 8 + 2 * thr;
            float2 cq = *reinterpret_cast<const float2*>(&sm.csq2[b][cc]);
            ll[nt][0] = pacc[nt][0] - cq.x;
            ll[nt][1] = pacc[nt][1] - cq.y;
            ll[nt][2] = pacc[nt][2] - cq.x;
            ll[nt][3] = pacc[nt][3] - cq.y;
        }
        float cm0 = fmaxf(fmaxf(ll[0][0], ll[0][1]), fmaxf(ll[1][0], ll[1][1]));
        float cm1 = fmaxf(fmaxf(ll[0][2], ll[0][3]), fmaxf(ll[1][2], ll[1][3]));
        cm0 = fmaxf(cm0, __shfl_xor_sync(0xffffffffu, cm0, 1));
        cm0 = fmaxf(cm0, __shfl_xor_sync(0xffffffffu, cm0, 2));
        cm1 = fmaxf(cm1, __shfl_xor_sync(0xffffffffu, cm1, 1));
        cm1 = fmaxf(cm1, __shfl_xor_sync(0xffffffffu, cm1, 2));
        if (thr == 0) {
            sm.halfmax[half][r0] = cm0;
            sm.halfmax[half][r1] = cm1;
        }
        __syncthreads();   // sync2a: halfmax visible

        // ---- combine halves, update running max, publish factors, emit P ----
        {
            float g0 = fmaxf(sm.halfmax[0][r0], sm.halfmax[1][r0]);
            float g1 = fmaxf(sm.halfmax[0][r1], sm.halfmax[1][r1]);
            float Mn0 = fmaxf(M0, g0), Mn1 = fmaxf(M1, g1);
            float f0 = fast_exp2(M0 - Mn0);
            float f1 = fast_exp2(M1 - Mn1);
            if (half == 0 && thr == 0) {
                sm.factor[r0] = f0;
                sm.factor[r1] = f1;
            }
            M0 = Mn0; M1 = Mn1;
            float cs0 = 0.f, cs1 = 0.f;
            #pragma unroll
            for (int nt = 0; nt < 2; nt++) {
                const int e = half * 8 + nt * 4 + thr;
                float p0 = fast_exp2(ll[nt][0] - Mn0);
                float p1 = fast_exp2(ll[nt][1] - Mn0);
                float p2 = fast_exp2(ll[nt][2] - Mn1);
                float p3 = fast_exp2(ll[nt][3] - Mn1);
                uint32_t h01 = pack_h2(p0, p1);
                uint32_t h23 = pack_h2(p2, p3);
                sm.p2[b][r0][e] = h01;
                sm.p2[b][r1][e] = h23;
                float2 q01 = h2f2(h01), q23 = h2f2(h23);
                cs0 += q01.x + q01.y;
                cs1 += q23.x + q23.y;
            }
            sacc0 = sacc0 * f0 + cs0;
            sacc1 = sacc1 * f1 + cs1;
        }
        __syncthreads();   // sync2b: P + factors visible

        // ---- GEMM2: rescale acc if needed, then acc += P @ V ----
        {
            const int mrow = rw * 32 + grp;
            float f[4];
            f[0] = sm.factor[mrow];
            f[1] = sm.factor[mrow + 8];
            f[2] = sm.factor[mrow + 16];
            f[3] = sm.factor[mrow + 24];
            bool need = (f[0] < 1.f) | (f[1] < 1.f) | (f[2] < 1.f) | (f[3] < 1.f);
            if (__any_sync(0xffffffffu, need)) {
                #pragma unroll
                for (int mt = 0; mt < 2; mt++)
                    #pragma unroll
                    for (int nt = 0; nt < 8; nt++) {
                        acc[mt][nt][0] *= f[2*mt];
                        acc[mt][nt][1] *= f[2*mt];
                        acc[mt][nt][2] *= f[2*mt+1];
                        acc[mt][nt][3] *= f[2*mt+1];
                    }
            }
            uint32_t a[2][2][4];
            #pragma unroll
            for (int mt = 0; mt < 2; mt++) {
                const int m = rw * 32 + mt * 16 + grp;
                #pragma unroll
                for (int kt2 = 0; kt2 < 2; kt2++) {
                    a[mt][kt2][0] = sm.p2[b][m][8 * kt2 + thr];
                    a[mt][kt2][1] = sm.p2[b][m + 8][8 * kt2 + thr];
                    a[mt][kt2][2] = sm.p2[b][m][8 * kt2 + thr + 4];
                    a[mt][kt2][3] = sm.p2[b][m + 8][8 * kt2 + thr + 4];
                }
            }
            #pragma unroll
            for (int nt = 0; nt < 8; nt++) {
                const int n = wc * 64 + nt * 8 + grp;
                #pragma unroll
                for (int kt2 = 0; kt2 < 2; kt2++) {
                    const uint32_t b0 = sm.vt2[b][n][8 * kt2 + thr];
                    const uint32_t b1 = sm.vt2[b][n][8 * kt2 + thr + 4];
                    mma16(acc[0][nt], a[0][kt2], b0, b1);
                    mma16(acc[1][nt], a[1][kt2], b0, b1);
                }
            }
        }
    }

    // ---- row sums: reduce over thr quad, publish per half ----
    sacc0 += __shfl_xor_sync(0xffffffffu, sacc0, 1);
    sacc0 += __shfl_xor_sync(0xffffffffu, sacc0, 2);
    sacc1 += __shfl_xor_sync(0xffffffffu, sacc1, 1);
    sacc1 += __shfl_xor_sync(0xffffffffu, sacc1, 2);
    if (thr == 0) {
        sm.rowsum[half][r0] = sacc0;
        sm.rowsum[half][r1] = sacc1;
    }
    __syncthreads();

    // ---- epilogue: normalize + store ----
    #pragma unroll
    for (int mt = 0; mt < 2; mt++) {
        const int row0 = rw * 32 + mt * 16 + grp;
        const float inv0 = 1.0f / (sm.rowsum[0][row0]     + sm.rowsum[1][row0]);
        const float inv1 = 1.0f / (sm.rowsum[0][row0 + 8] + sm.rowsum[1][row0 + 8]);
        float* o0 = out + (size_t)(n0 + row0) * DOUT;
        float* o1 = out + (size_t)(n0 + row0 + 8) * DOUT;
        #pragma unroll
        for (int nt = 0; nt < 8; nt++) {
            const int col = wc * 64 + nt * 8 + 2 * thr;
            *reinterpret_cast<float2*>(o0 + col) =
                make_float2(acc[mt][nt][0] * inv0, acc[mt][nt][1] * inv0);
            *reinterpret_cast<float2*>(o1 + col) =
                make_float2(acc[mt][nt][2] * inv1, acc[mt][nt][3] * inv1);
        }
    }
}

extern "C" void kernel_launch(void* const* d_in, const int* in_sizes, int n_in,
                              void* d_out, int out_size)
{
    const float* x      = (const float*)d_in[0];   // (65536, 64)
    const float* ctrs   = (const float*)d_in[1];   // (1024, 64)
    const float* values = (const float*)d_in[2];   // (1024, 256)
    const float* s      = (const float*)d_in[3];   // (64,)
    float* out          = (float*)d_out;           // (65536, 256)

    const int smem_bytes = (int)sizeof(Smem);
    cudaFuncSetAttribute(attnn_kernel,
                         cudaFuncAttributeMaxDynamicSharedMemorySize, smem_bytes);
    attnn_kernel<<<NROWS / BM, THREADS, smem_bytes>>>(x, ctrs, values, s, out);
}

// round 17
// speedup vs baseline: 1.7679x; 1.1394x over previous
#include <cuda_runtime.h>
#include <cuda_fp16.h>
#include <cstdint>

#define NROWS  65536
#define DIN    64
#define NC     1024
#define DOUT   256
#define BM     64
#define BK     32
#define NCHUNK (NC / BK)
#define THREADS 256
#define LOG2E  1.4426950408889634f

struct Smem {
    uint32_t cth[2][BK][36];     // centers hi (fp16x2 d-pairs) [n][e]
    uint32_t ctl[2][BK][36];     // centers lo
    uint32_t vt2[2][DOUT][20];   // V (fp16x2 k-pairs) [n][e]
    uint32_t p2[2][BM][20];      // P (fp16x2 k-pairs) [m][e]
    float    csq2[2][BK];        // (sum c^2 s) * log2e
    float    factor[2][BM];      // acc rescale per row (double-buffered)
    float    rowsum[BM];
    float    s[DIN];
};

__device__ __forceinline__ float fast_exp2(float f) {
    float r; asm("ex2.approx.f32 %0, %1;" : "=f"(r) : "f"(f)); return r;
}
__device__ __forceinline__ uint32_t pack_h2(float lo, float hi) {
    uint32_t d; asm("cvt.rn.f16x2.f32 %0, %1, %2;" : "=r"(d) : "f"(hi), "f"(lo)); return d;
}
__device__ __forceinline__ float2 h2f2(uint32_t h) {
    __half2 hh = *reinterpret_cast<__half2*>(&h);
    return __half22float2(hh);
}
__device__ __forceinline__ void mma16(float* d, const uint32_t* a,
                                      uint32_t b0, uint32_t b1) {
    asm volatile(
        "mma.sync.aligned.m16n8k16.row.col.f32.f16.f16.f32 "
        "{%0,%1,%2,%3}, {%4,%5,%6,%7}, {%8,%9}, {%0,%1,%2,%3};"
        : "+f"(d[0]), "+f"(d[1]), "+f"(d[2]), "+f"(d[3])
        : "r"(a[0]), "r"(a[1]), "r"(a[2]), "r"(a[3]), "r"(b0), "r"(b1));
}
#define BAR_SYNC(id, cnt)   asm volatile("bar.sync %0, %1;"   :: "r"(id), "r"(cnt) : "memory")
#define BAR_ARRIVE(id, cnt) asm volatile("bar.arrive %0, %1;" :: "r"(id), "r"(cnt) : "memory")

__global__ void __launch_bounds__(THREADS, 1)
attnn_kernel(const float* __restrict__ x,
             const float* __restrict__ ctrs,
             const float* __restrict__ values,
             const float* __restrict__ s_in,
             float* __restrict__ out)
{
    extern __shared__ char raw[];
    Smem& sm = *reinterpret_cast<Smem*>(raw);

    const int tid  = threadIdx.x;
    const int lane = tid & 31;
    const int wid  = tid >> 5;
    const int n0   = blockIdx.x * BM;
    const int grp  = lane >> 2;
    const int thr  = lane & 3;
    const bool isA = (wid < 4);

    if (tid < DIN) sm.s[tid] = s_in[tid];
    __syncthreads();

    // ---- stage scaled x (2*log2e*s*x) into scratch overlaying vt2 ----
    float* xs = reinterpret_cast<float*>(&sm.vt2[0][0][0]);   // [64][68]
    {
        const int r = tid >> 2, q = tid & 3;
        const float* xp = x + (size_t)(n0 + r) * DIN + 16 * q;
        #pragma unroll
        for (int m = 0; m < 4; m++) {
            float4 v = *reinterpret_cast<const float4*>(xp + 4 * m);
            const int d = 16 * q + 4 * m;
            const float kf = 2.0f * LOG2E;
            float4 t = make_float4(kf * v.x * sm.s[d+0], kf * v.y * sm.s[d+1],
                                   kf * v.z * sm.s[d+2], kf * v.w * sm.s[d+3]);
            *reinterpret_cast<float4*>(&xs[r * 68 + d]) = t;
        }
    }

    // ---- per-group prefetch of chunk 0 (regs only) ----
    float4 cp[4];
    uint32_t vh0[16], vh1[16];
    float sreg[16];
    const int ck = tid >> 2;
    const int dq = tid & 3;
    const int tb = tid - 128;
    if (isA) {
        #pragma unroll
        for (int u = 0; u < 16; u++) sreg[u] = sm.s[dq * 16 + u];
        const float* cpp = ctrs + (size_t)ck * DIN + dq * 16;
        #pragma unroll
        for (int i = 0; i < 4; i++)
            cp[i] = *reinterpret_cast<const float4*>(cpp + 4 * i);
    } else {
        const float* vp = values + tb;
        #pragma unroll
        for (int e = 0; e < 16; e++) {
            float a0 = vp[(size_t)(2 * e) * DOUT];
            float a1 = vp[(size_t)(2 * e + 1) * DOUT];
            float b0 = vp[(size_t)(2 * e) * DOUT + 128];
            float b1 = vp[(size_t)(2 * e + 1) * DOUT + 128];
            vh0[e] = pack_h2(a0, a1);
            vh1[e] = pack_h2(b0, b1);
        }
    }
    __syncthreads();   // xs visible

    // ---- A: persistent x hi/lo fp16 fragments ----
    uint32_t ah[4][4], al[4][4];
    if (isA) {
        const int m0 = 16 * wid + grp;
        #pragma unroll
        for (int kt = 0; kt < 4; kt++) {
            #pragma unroll
            for (int rr = 0; rr < 2; rr++) {
                const int m = m0 + 8 * rr;
                float2 v0 = *reinterpret_cast<const float2*>(&xs[m * 68 + 2 * thr + 16 * kt]);
                float2 v1 = *reinterpret_cast<const float2*>(&xs[m * 68 + 2 * thr + 8 + 16 * kt]);
                uint32_t h0 = pack_h2(v0.x, v0.y);
                float2 hf0 = h2f2(h0);
                uint32_t l0 = pack_h2(v0.x - hf0.x, v0.y - hf0.y);
                uint32_t h1 = pack_h2(v1.x, v1.y);
                float2 hf1 = h2f2(h1);
                uint32_t l1 = pack_h2(v1.x - hf1.x, v1.y - hf1.y);
                ah[kt][rr] = h0; ah[kt][rr + 2] = h1;
                al[kt][rr] = l0; al[kt][rr + 2] = l1;
            }
        }
    }
    __syncthreads();   // xs scratch free -> vt2 usable

    if (isA) {
        // ================= GROUP A: GEMM1 + softmax producer =================
        const int r0 = 16 * wid + grp, r1 = r0 + 8;
        float sacc0 = 0.f, sacc1 = 0.f;
        float M0 = -1e30f, M1 = -1e30f;

        for (int c = 0; c < NCHUNK; c++) {
            const int b = c & 1;
            const int bar_ready = b ? 6 : 1;   // "P(b) ready"
            const int bar_free  = b ? 7 : 2;   // "P(b) free"
            {
                float cv[16] = {cp[0].x, cp[0].y, cp[0].z, cp[0].w,
                                cp[1].x, cp[1].y, cp[1].z, cp[1].w,
                                cp[2].x, cp[2].y, cp[2].z, cp[2].w,
                                cp[3].x, cp[3].y, cp[3].z, cp[3].w};
                uint32_t hw[8], lw[8];
                #pragma unroll
                for (int w = 0; w < 8; w++) {
                    hw[w] = pack_h2(cv[2*w], cv[2*w+1]);
                    float2 hf = h2f2(hw[w]);
                    lw[w] = pack_h2(cv[2*w] - hf.x, cv[2*w+1] - hf.y);
                }
                *reinterpret_cast<uint4*>(&sm.cth[b][ck][8 * dq]) =
                    make_uint4(hw[0], hw[1], hw[2], hw[3]);
                *reinterpret_cast<uint4*>(&sm.cth[b][ck][8 * dq + 4]) =
                    make_uint4(hw[4], hw[5], hw[6], hw[7]);
                *reinterpret_cast<uint4*>(&sm.ctl[b][ck][8 * dq]) =
                    make_uint4(lw[0], lw[1], lw[2], lw[3]);
                *reinterpret_cast<uint4*>(&sm.ctl[b][ck][8 * dq + 4]) =
                    make_uint4(lw[4], lw[5], lw[6], lw[7]);
                float part = 0.f;
                #pragma unroll
                for (int u = 0; u < 16; u++) part += cv[u] * cv[u] * sreg[u];
                part += __shfl_xor_sync(0xffffffffu, part, 1);
                part += __shfl_xor_sync(0xffffffffu, part, 2);
                if (dq == 0) sm.csq2[b][ck] = part * LOG2E;
            }
            BAR_SYNC(3, 128);   // A-local: tiles visible

            if (c + 1 < NCHUNK) {
                const float* cpp = ctrs + (size_t)((c + 1) * BK + ck) * DIN + dq * 16;
                #pragma unroll
                for (int i = 0; i < 4; i++)
                    cp[i] = *reinterpret_cast<const float4*>(cpp + 4 * i);
            }

            float pacc[4][4];
            #pragma unroll
            for (int nt = 0; nt < 4; nt++)
                #pragma unroll
                for (int u = 0; u < 4; u++) pacc[nt][u] = 0.f;
            #pragma unroll
            for (int nt = 0; nt < 4; nt++) {
                const int n = nt * 8 + grp;
                #pragma unroll
                for (int kt = 0; kt < 4; kt++) {
                    const uint32_t bh0 = sm.cth[b][n][8 * kt + thr];
                    const uint32_t bh1 = sm.cth[b][n][8 * kt + thr + 4];
                    const uint32_t bl0 = sm.ctl[b][n][8 * kt + thr];
                    const uint32_t bl1 = sm.ctl[b][n][8 * kt + thr + 4];
                    mma16(pacc[nt], ah[kt], bh0, bh1);
                    mma16(pacc[nt], ah[kt], bl0, bl1);
                    mma16(pacc[nt], al[kt], bh0, bh1);
                }
            }

            float ll[4][4];
            #pragma unroll
            for (int nt = 0; nt < 4; nt++) {
                const int cc = nt * 8 + 2 * thr;
                float2 cq = *reinterpret_cast<const float2*>(&sm.csq2[b][cc]);
                ll[nt][0] = pacc[nt][0] - cq.x;
                ll[nt][1] = pacc[nt][1] - cq.y;
                ll[nt][2] = pacc[nt][2] - cq.x;
                ll[nt][3] = pacc[nt][3] - cq.y;
            }
            float cm0 = fmaxf(fmaxf(ll[0][0], ll[0][1]), fmaxf(ll[1][0], ll[1][1]));
            cm0 = fmaxf(cm0, fmaxf(fmaxf(ll[2][0], ll[2][1]), fmaxf(ll[3][0], ll[3][1])));
            float cm1 = fmaxf(fmaxf(ll[0][2], ll[0][3]), fmaxf(ll[1][2], ll[1][3]));
            cm1 = fmaxf(cm1, fmaxf(fmaxf(ll[2][2], ll[2][3]), fmaxf(ll[3][2], ll[3][3])));
            cm0 = fmaxf(cm0, __shfl_xor_sync(0xffffffffu, cm0, 1));
            cm0 = fmaxf(cm0, __shfl_xor_sync(0xffffffffu, cm0, 2));
            cm1 = fmaxf(cm1, __shfl_xor_sync(0xffffffffu, cm1, 1));
            cm1 = fmaxf(cm1, __shfl_xor_sync(0xffffffffu, cm1, 2));
            const float Mn0 = fmaxf(M0, cm0), Mn1 = fmaxf(M1, cm1);
            const float f0 = fast_exp2(M0 - Mn0);
            const float f1 = fast_exp2(M1 - Mn1);
            M0 = Mn0; M1 = Mn1;

            if (c >= 2) BAR_SYNC(bar_free, 256);   // B freed P(b) from chunk c-2

            if (thr == 0) {
                sm.factor[b][r0] = f0;
                sm.factor[b][r1] = f1;
            }
            float cs0 = 0.f, cs1 = 0.f;
            #pragma unroll
            for (int nt = 0; nt < 4; nt++) {
                float p0 = fast_exp2(ll[nt][0] - Mn0);
                float p1 = fast_exp2(ll[nt][1] - Mn0);
                float p2 = fast_exp2(ll[nt][2] - Mn1);
                float p3 = fast_exp2(ll[nt][3] - Mn1);
                uint32_t h01 = pack_h2(p0, p1);
                uint32_t h23 = pack_h2(p2, p3);
                sm.p2[b][r0][4 * nt + thr] = h01;
                sm.p2[b][r1][4 * nt + thr] = h23;
                float2 q01 = h2f2(h01), q23 = h2f2(h23);
                cs0 += q01.x + q01.y;
                cs1 += q23.x + q23.y;
            }
            sacc0 = sacc0 * f0 + cs0;
            sacc1 = sacc1 * f1 + cs1;
            BAR_ARRIVE(bar_ready, 256);   // P(b) + factors ready
        }

        sacc0 += __shfl_xor_sync(0xffffffffu, sacc0, 1);
        sacc0 += __shfl_xor_sync(0xffffffffu, sacc0, 2);
        sacc1 += __shfl_xor_sync(0xffffffffu, sacc1, 1);
        sacc1 += __shfl_xor_sync(0xffffffffu, sacc1, 2);
        if (thr == 0) {
            sm.rowsum[r0] = sacc0;
            sm.rowsum[r1] = sacc1;
        }
        BAR_ARRIVE(5, 256);
    } else {
        // ================= GROUP B: GEMM2 consumer =================
        const int bw = wid - 4;
        const int rw = bw >> 1;
        const int wc = bw & 1;
        float acc[2][16][4];
        #pragma unroll
        for (int mt = 0; mt < 2; mt++)
            #pragma unroll
            for (int nt = 0; nt < 16; nt++)
                #pragma unroll
                for (int u = 0; u < 4; u++) acc[mt][nt][u] = 0.f;

        for (int c = 0; c < NCHUNK; c++) {
            const int b = c & 1;
            const int bar_ready = b ? 6 : 1;
            const int bar_free  = b ? 7 : 2;
            #pragma unroll
            for (int j = 0; j < 4; j++) {
                *reinterpret_cast<uint4*>(&sm.vt2[b][tb][4 * j]) =
                    make_uint4(vh0[4*j], vh0[4*j+1], vh0[4*j+2], vh0[4*j+3]);
                *reinterpret_cast<uint4*>(&sm.vt2[b][tb + 128][4 * j]) =
                    make_uint4(vh1[4*j], vh1[4*j+1], vh1[4*j+2], vh1[4*j+3]);
            }
            BAR_SYNC(4, 128);   // B-local: vt visible

            if (c + 1 < NCHUNK) {
                const float* vp = values + (size_t)(c + 1) * BK * DOUT + tb;
                #pragma unroll
                for (int e = 0; e < 16; e++) {
                    float a0 = vp[(size_t)(2 * e) * DOUT];
                    float a1 = vp[(size_t)(2 * e + 1) * DOUT];
                    float b0 = vp[(size_t)(2 * e) * DOUT + 128];
                    float b1 = vp[(size_t)(2 * e + 1) * DOUT + 128];
                    vh0[e] = pack_h2(a0, a1);
                    vh1[e] = pack_h2(b0, b1);
                }
            }

            BAR_SYNC(bar_ready, 256);   // wait P(b)

            {
                const int mrow = rw * 32 + grp;
                float f[4];
                f[0] = sm.factor[b][mrow];
                f[1] = sm.factor[b][mrow + 8];
                f[2] = sm.factor[b][mrow + 16];
                f[3] = sm.factor[b][mrow + 24];
                bool need = (f[0] < 1.f) | (f[1] < 1.f) | (f[2] < 1.f) | (f[3] < 1.f);
                if (__any_sync(0xffffffffu, need)) {
                    #pragma unroll
                    for (int mt = 0; mt < 2; mt++)
                        #pragma unroll
                        for (int nt = 0; nt < 16; nt++) {
                            acc[mt][nt][0] *= f[2*mt];
                            acc[mt][nt][1] *= f[2*mt];
                            acc[mt][nt][2] *= f[2*mt+1];
                            acc[mt][nt][3] *= f[2*mt+1];
                        }
                }
            }
            uint32_t a[2][2][4];
            #pragma unroll
            for (int mt = 0; mt < 2; mt++) {
                const int m = rw * 32 + mt * 16 + grp;
                #pragma unroll
                for (int kt2 = 0; kt2 < 2; kt2++) {
                    a[mt][kt2][0] = sm.p2[b][m][8 * kt2 + thr];
                    a[mt][kt2][1] = sm.p2[b][m + 8][8 * kt2 + thr];
                    a[mt][kt2][2] = sm.p2[b][m][8 * kt2 + thr + 4];
                    a[mt][kt2][3] = sm.p2[b][m + 8][8 * kt2 + thr + 4];
                }
            }
            #pragma unroll
            for (int nt = 0; nt < 16; nt++) {
                const int n = wc * 128 + nt * 8 + grp;
                #pragma unroll
                for (int kt2 = 0; kt2 < 2; kt2++) {
                    const uint32_t b0 = sm.vt2[b][n][8 * kt2 + thr];
                    const uint32_t b1 = sm.vt2[b][n][8 * kt2 + thr + 4];
                    mma16(acc[0][nt], a[0][kt2], b0, b1);
                    mma16(acc[1][nt], a[1][kt2], b0, b1);
                }
            }
            if (c < NCHUNK - 2) BAR_ARRIVE(bar_free, 256);   // P(b) free
        }
        BAR_SYNC(5, 256);   // rowsum ready

        #pragma unroll
        for (int mt = 0; mt < 2; mt++) {
            const int row0 = rw * 32 + mt * 16 + grp;
            const float inv0 = 1.0f / sm.rowsum[row0];
            const float inv1 = 1.0f / sm.rowsum[row0 + 8];
            float* o0 = out + (size_t)(n0 + row0) * DOUT;
            float* o1 = out + (size_t)(n0 + row0 + 8) * DOUT;
            #pragma unroll
            for (int nt = 0; nt < 16; nt++) {
                const int col = wc * 128 + nt * 8 + 2 * thr;
                *reinterpret_cast<float2*>(o0 + col) =
                    make_float2(acc[mt][nt][0] * inv0, acc[mt][nt][1] * inv0);
                *reinterpret_cast<float2*>(o1 + col) =
                    make_float2(acc[mt][nt][2] * inv1, acc[mt][nt][3] * inv1);
            }
        }
    }
}

extern "C" void kernel_launch(void* const* d_in, const int* in_sizes, int n_in,
                              void* d_out, int out_size)
{
    const float* x      = (const float*)d_in[0];   // (65536, 64)
    const float* ctrs   = (const float*)d_in[1];   // (1024, 64)
    const float* values = (const float*)d_in[2];   // (1024, 256)
    const float* s      = (const float*)d_in[3];   // (64,)
    float* out          = (float*)d_out;           // (65536, 256)

    const int smem_bytes = (int)sizeof(Smem);
    cudaFuncSetAttribute(attnn_kernel,
                         cudaFuncAttributeMaxDynamicSharedMemorySize, smem_bytes);
    attnn_kernel<<<NROWS / BM, THREADS, smem_bytes>>>(x, ctrs, values, s, out);
}